// round 11
// baseline (speedup 1.0000x reference)
#include <cuda_runtime.h>
#include <cuda_bf16.h>

// Batched 1024-point FFT, real input, complex output ([real block][imag block]).
// Two real rows per complex FFT (z = xa + i*xb), Hermitian unpack at the end.
// 1024 = 16(n2) x [64 = 4(m1) x 16(m2)]; Z index = 256*j1 + 16*j2 + k2.
// R11: R10 body run TWICE per CTA (grid 8192, sequential, no prefetch state)
// to halve per-CTA prologue/epilogue edges. Regs stay ~40 (state reused).

#define N_FFT 1024
#define BATCH 32768
#define NPAIRS (BATCH / 2)   // 16384
#define NBLK (NPAIRS / 2)    // 8192
#define TPB 64

#define S1 17             // float2 stride for ex1/ex2 row exchanges
#define BUFSZ 1152        // float2 buffer (>= 64*S1=1088, >= staging 1024, >= PHYS(1023)=1086)

#define PHYS(k) ((k) + ((k) >> 4))

// cos/sin(-2*pi*t/16), t = 0..15
#define W16_TABLES \
    const float C[16] = { 1.0f,  0.92387953f,  0.70710678f,  0.38268343f, \
                          0.0f, -0.38268343f, -0.70710678f, -0.92387953f, \
                         -1.0f, -0.92387953f, -0.70710678f, -0.38268343f, \
                          0.0f,  0.38268343f,  0.70710678f,  0.92387953f }; \
    const float S[16] = { 0.0f, -0.38268343f, -0.70710678f, -0.92387953f, \
                         -1.0f, -0.92387953f, -0.70710678f, -0.38268343f, \
                          0.0f,  0.38268343f,  0.70710678f,  0.92387953f, \
                          1.0f,  0.92387953f,  0.70710678f,  0.38268343f };

// Literal cos/sin(-2*pi*t/64), t = 0..63.
#define W64_TABLES \
    const float C64[64] = { \
         1.00000000f,  0.99518473f,  0.98078528f,  0.95694034f,  0.92387953f,  0.88192126f,  0.83146961f,  0.77301045f, \
         0.70710678f,  0.63439328f,  0.55557023f,  0.47139674f,  0.38268343f,  0.29028468f,  0.19509032f,  0.09801714f, \
         0.00000000f, -0.09801714f, -0.19509032f, -0.29028468f, -0.38268343f, -0.47139674f, -0.55557023f, -0.63439328f, \
        -0.70710678f, -0.77301045f, -0.83146961f, -0.88192126f, -0.92387953f, -0.95694034f, -0.98078528f, -0.99518473f, \
        -1.00000000f, -0.99518473f, -0.98078528f, -0.95694034f, -0.92387953f, -0.88192126f, -0.83146961f, -0.77301045f, \
        -0.70710678f, -0.63439328f, -0.55557023f, -0.47139674f, -0.38268343f, -0.29028468f, -0.19509032f, -0.09801714f, \
        -0.00000000f,  0.09801714f,  0.19509032f,  0.29028468f,  0.38268343f,  0.47139674f,  0.55557023f,  0.63439328f, \
         0.70710678f,  0.77301045f,  0.83146961f,  0.88192126f,  0.92387953f,  0.95694034f,  0.98078528f,  0.99518473f }; \
    const float S64[64] = { \
        -0.00000000f, -0.09801714f, -0.19509032f, -0.29028468f, -0.38268343f, -0.47139674f, -0.55557023f, -0.63439328f, \
        -0.70710678f, -0.77301045f, -0.83146961f, -0.88192126f, -0.92387953f, -0.95694034f, -0.98078528f, -0.99518473f, \
        -1.00000000f, -0.99518473f, -0.98078528f, -0.95694034f, -0.92387953f, -0.88192126f, -0.83146961f, -0.77301045f, \
        -0.70710678f, -0.63439328f, -0.55557023f, -0.47139674f, -0.38268343f, -0.29028468f, -0.19509032f, -0.09801714f, \
         0.00000000f,  0.09801714f,  0.19509032f,  0.29028468f,  0.38268343f,  0.47139674f,  0.55557023f,  0.63439328f, \
         0.70710678f,  0.77301045f,  0.83146961f,  0.88192126f,  0.92387953f,  0.95694034f,  0.98078528f,  0.99518473f, \
         1.00000000f,  0.99518473f,  0.98078528f,  0.95694034f,  0.92387953f,  0.88192126f,  0.83146961f,  0.77301045f, \
         0.70710678f,  0.63439328f,  0.55557023f,  0.47139674f,  0.38268343f,  0.29028468f,  0.19509032f,  0.09801714f };

// Complex FFT-16, natural order in/out (radix-4 x radix-4).
__device__ __forceinline__ void fft16c(float* ar, float* ai) {
    W16_TABLES
    float zr[16], zi[16];
    {
        float t0r = ar[0] + ar[8],  t0i = ai[0] + ai[8];
        float t1r = ar[0] - ar[8],  t1i = ai[0] - ai[8];
        float t2r = ar[4] + ar[12], t2i = ai[4] + ai[12];
        float t3r = ar[4] - ar[12], t3i = ai[4] - ai[12];
        zr[0] = t0r + t2r; zi[0] = t0i + t2i;
        zr[1] = t1r + t3i; zi[1] = t1i - t3r;
        zr[2] = t0r - t2r; zi[2] = t0i - t2i;
        zr[3] = t1r - t3i; zi[3] = t1i + t3r;
    }
#pragma unroll
    for (int a = 1; a < 4; a++) {
        float t0r = ar[a] + ar[a+8],  t0i = ai[a] + ai[a+8];
        float t1r = ar[a] - ar[a+8],  t1i = ai[a] - ai[a+8];
        float t2r = ar[a+4] + ar[a+12], t2i = ai[a+4] + ai[a+12];
        float t3r = ar[a+4] - ar[a+12], t3i = ai[a+4] - ai[a+12];
        float y1r = t1r + t3i, y1i = t1i - t3r;
        float y2r = t0r - t2r, y2i = t0i - t2i;
        float y3r = t1r - t3i, y3i = t1i + t3r;
        zr[4*a+0] = t0r + t2r; zi[4*a+0] = t0i + t2i;
        { const float c = C[a], s = S[a];
          zr[4*a+1] = c*y1r - s*y1i; zi[4*a+1] = c*y1i + s*y1r; }
        { const float c = C[(2*a)&15], s = S[(2*a)&15];
          zr[4*a+2] = c*y2r - s*y2i; zi[4*a+2] = c*y2i + s*y2r; }
        { const float c = C[(3*a)&15], s = S[(3*a)&15];
          zr[4*a+3] = c*y3r - s*y3i; zi[4*a+3] = c*y3i + s*y3r; }
    }
#pragma unroll
    for (int k2 = 0; k2 < 4; k2++) {
        float t0r = zr[k2]   + zr[k2+8],  t0i = zi[k2]   + zi[k2+8];
        float t1r = zr[k2]   - zr[k2+8],  t1i = zi[k2]   - zi[k2+8];
        float t2r = zr[k2+4] + zr[k2+12], t2i = zi[k2+4] + zi[k2+12];
        float t3r = zr[k2+4] - zr[k2+12], t3i = zi[k2+4] - zi[k2+12];
        ar[k2]    = t0r + t2r;  ai[k2]    = t0i + t2i;
        ar[k2+4]  = t1r + t3i;  ai[k2+4]  = t1i - t3r;
        ar[k2+8]  = t0r - t2r;  ai[k2+8]  = t0i - t2i;
        ar[k2+12] = t1r - t3i;  ai[k2+12] = t1i + t3r;
    }
}

// Stage-A twiddle: multiply regs j=1..15 by w^j, w = exp(i*base); sincos per j.
__device__ __forceinline__ void twiddle15p(float* ar, float* ai, float base) {
#pragma unroll
    for (int j = 1; j < 16; j++) {
        float s, c;
        __sincosf(base * (float)j, &s, &c);
        float tr = c * ar[j] - s * ai[j];
        ai[j]    = c * ai[j] + s * ar[j];
        ar[j]    = tr;
    }
}

// Stage-B twiddle: regs j=1..15 *= W_64^{M1*j}, literal immediates.
template <int M1>
__device__ __forceinline__ void twiddleB(float* ar, float* ai) {
    W64_TABLES
#pragma unroll
    for (int j = 1; j < 16; j++) {
        const float c = C64[(M1 * j) & 63];
        const float s = S64[(M1 * j) & 63];
        float tr = c * ar[j] - s * ai[j];
        ai[j]    = c * ai[j] + s * ar[j];
        ar[j]    = tr;
    }
}

// One full pair: stage -> FFT -> unpack -> store. sm is the block's buffer.
__device__ __forceinline__ void do_pair(const float* __restrict__ x,
                                        float* __restrict__ out,
                                        float2* sm, int t, int pair) {
    float* lin = (float*)sm;
    const int rowA = 2 * pair;

    // ---- stage rows a,b into smem via cp.async ----
    {
        const float4* xa4 = (const float4*)(x + (size_t)rowA * N_FFT);
        unsigned sbase = (unsigned)__cvta_generic_to_shared(lin);
#pragma unroll
        for (int c = 0; c < 8; c++) {
            int f = t + 64 * c;
            asm volatile("cp.async.cg.shared.global [%0], [%1], 16;\n"
                         :: "r"(sbase + f * 16), "l"(xa4 + f));
        }
        asm volatile("cp.async.commit_group;\n");
        asm volatile("cp.async.wait_group 0;\n");
    }
    __syncthreads();

    float ar[16], ai[16];
#pragma unroll
    for (int n2 = 0; n2 < 16; n2++) {
        ar[n2] = lin[t + 64 * n2];
        ai[n2] = lin[1024 + t + 64 * n2];
    }
    __syncthreads();

    // stage A
    fft16c(ar, ai);
    twiddle15p(ar, ai, (float)t * (-6.2831853071795864769f / 1024.0f));

#pragma unroll
    for (int j = 0; j < 16; j++)
        sm[t * S1 + j] = make_float2(ar[j], ai[j]);
    __syncthreads();

    // stage B
    const int m1 = t >> 4;
    const int k2 = t & 15;
#pragma unroll
    for (int m2 = 0; m2 < 16; m2++) {
        float2 v = sm[(m1 + 4 * m2) * S1 + k2];
        ar[m2] = v.x; ai[m2] = v.y;
    }
    __syncthreads();

    fft16c(ar, ai);
    if (m1 == 1)      twiddleB<1>(ar, ai);
    else if (m1 == 2) twiddleB<2>(ar, ai);
    else if (m1 == 3) twiddleB<3>(ar, ai);

#pragma unroll
    for (int j = 0; j < 16; j++)
        sm[(m1 * 16 + j) * S1 + k2] = make_float2(ar[j], ai[j]);
    __syncthreads();

    // stage C
    {
        const int j2 = t >> 2;
        const int cq = t & 3;
        float br[4][4], bi[4][4];
#pragma unroll
        for (int mm = 0; mm < 4; mm++) {
#pragma unroll
            for (int d = 0; d < 4; d++) {
                float2 v = sm[(mm * 16 + j2) * S1 + 4 * cq + d];
                br[mm][d] = v.x; bi[mm][d] = v.y;
            }
        }
        __syncthreads();

        const int kb0 = 16 * j2 + 4 * cq;
#pragma unroll
        for (int d = 0; d < 4; d++) {
            float t0r = br[0][d] + br[2][d], t0i = bi[0][d] + bi[2][d];
            float t1r = br[0][d] - br[2][d], t1i = bi[0][d] - bi[2][d];
            float t2r = br[1][d] + br[3][d], t2i = bi[1][d] + bi[3][d];
            float t3r = br[1][d] - br[3][d], t3i = bi[1][d] - bi[3][d];
            const int kb = kb0 + d;
            sm[PHYS(kb      )] = make_float2(t0r + t2r, t0i + t2i);
            sm[PHYS(kb + 256)] = make_float2(t1r + t3i, t1i - t3r);
            sm[PHYS(kb + 512)] = make_float2(t0r - t2r, t0i - t2i);
            sm[PHYS(kb + 768)] = make_float2(t1r - t3i, t1i + t3r);
        }
    }
    __syncthreads();

    // Hermitian unpack + coalesced float4 stores
    float* oRa = out + (size_t)rowA * N_FFT;
    float* oIa = out + (size_t)BATCH * N_FFT + (size_t)rowA * N_FFT;
    float* oRb = oRa + N_FFT;
    float* oIb = oIa + N_FFT;

#pragma unroll
    for (int u = 0; u < 4; u++) {
        const int k0 = 256 * u + 4 * t;
        const int km0 = (N_FFT - k0) & (N_FFT - 1);
        float4 xar, xai, xbr, xbi;
        float* pxar = &xar.x; float* pxai = &xai.x;
        float* pxbr = &xbr.x; float* pxbi = &xbi.x;
#pragma unroll
        for (int d = 0; d < 4; d++) {
            const int k  = k0 + d;
            const int km = (km0 - d) & (N_FFT - 1);
            float2 Z = sm[PHYS(k)];
            float2 M = sm[PHYS(km)];
            pxar[d] = 0.5f * (Z.x + M.x);
            pxai[d] = 0.5f * (Z.y - M.y);
            pxbr[d] = 0.5f * (Z.y + M.y);
            pxbi[d] = 0.5f * (M.x - Z.x);
        }
        *(float4*)(oRa + k0) = xar;
        *(float4*)(oIa + k0) = xai;
        *(float4*)(oRb + k0) = xbr;
        *(float4*)(oIb + k0) = xbi;
    }
    __syncthreads();   // unpack reads done before buffer reuse by next pair
}

__global__ __launch_bounds__(TPB, 24)
void fft1024_kernel(const float* __restrict__ x, float* __restrict__ out) {
    __shared__ __align__(16) float2 smem[BUFSZ];
    const int t = threadIdx.x;
    do_pair(x, out, smem, t, blockIdx.x);
    do_pair(x, out, smem, t, blockIdx.x + NBLK);
}

extern "C" void kernel_launch(void* const* d_in, const int* in_sizes, int n_in,
                              void* d_out, int out_size) {
    const float* x = (const float*)d_in[0];
    float* out = (float*)d_out;
    fft1024_kernel<<<NBLK, TPB>>>(x, out);
}

// round 12
// speedup vs baseline: 1.4657x; 1.4657x over previous
#include <cuda_runtime.h>
#include <cuda_bf16.h>

// Batched 1024-point FFT, real input, complex output ([real block][imag block]).
// Two real rows per complex FFT (z = xa + i*xb), Hermitian unpack at the end.
// 1024 = 16(n2) x [64 = 4(m1) x 16(m2)]; Z index = 256*j1 + 16*j2 + k2.
// FINAL (R10): 64-thread blocks, one row-pair per block, cp.async staging,
// stage-B twiddles as literal float immediates, launch_bounds(64,24) -> 40 regs.
// Measured: 63.97us, rel_err 3.1e-7; HBM 5.74 TB/s (achieved ceiling for this mix).

#define N_FFT 1024
#define BATCH 32768
#define TPB 64

#define S1 17             // float2 stride for ex1/ex2 row exchanges
#define BUFSZ 1152        // float2 buffer (>= 64*S1=1088, >= staging 1024, >= PHYS(1023)=1086)

#define PHYS(k) ((k) + ((k) >> 4))

// cos/sin(-2*pi*t/16), t = 0..15
#define W16_TABLES \
    const float C[16] = { 1.0f,  0.92387953f,  0.70710678f,  0.38268343f, \
                          0.0f, -0.38268343f, -0.70710678f, -0.92387953f, \
                         -1.0f, -0.92387953f, -0.70710678f, -0.38268343f, \
                          0.0f,  0.38268343f,  0.70710678f,  0.92387953f }; \
    const float S[16] = { 0.0f, -0.38268343f, -0.70710678f, -0.92387953f, \
                         -1.0f, -0.92387953f, -0.70710678f, -0.38268343f, \
                          0.0f,  0.38268343f,  0.70710678f,  0.92387953f, \
                          1.0f,  0.92387953f,  0.70710678f,  0.38268343f };

// Literal cos/sin(-2*pi*t/64), t = 0..63 (host-generated, float-rounded).
#define W64_TABLES \
    const float C64[64] = { \
         1.00000000f,  0.99518473f,  0.98078528f,  0.95694034f,  0.92387953f,  0.88192126f,  0.83146961f,  0.77301045f, \
         0.70710678f,  0.63439328f,  0.55557023f,  0.47139674f,  0.38268343f,  0.29028468f,  0.19509032f,  0.09801714f, \
         0.00000000f, -0.09801714f, -0.19509032f, -0.29028468f, -0.38268343f, -0.47139674f, -0.55557023f, -0.63439328f, \
        -0.70710678f, -0.77301045f, -0.83146961f, -0.88192126f, -0.92387953f, -0.95694034f, -0.98078528f, -0.99518473f, \
        -1.00000000f, -0.99518473f, -0.98078528f, -0.95694034f, -0.92387953f, -0.88192126f, -0.83146961f, -0.77301045f, \
        -0.70710678f, -0.63439328f, -0.55557023f, -0.47139674f, -0.38268343f, -0.29028468f, -0.19509032f, -0.09801714f, \
        -0.00000000f,  0.09801714f,  0.19509032f,  0.29028468f,  0.38268343f,  0.47139674f,  0.55557023f,  0.63439328f, \
         0.70710678f,  0.77301045f,  0.83146961f,  0.88192126f,  0.92387953f,  0.95694034f,  0.98078528f,  0.99518473f }; \
    const float S64[64] = { \
        -0.00000000f, -0.09801714f, -0.19509032f, -0.29028468f, -0.38268343f, -0.47139674f, -0.55557023f, -0.63439328f, \
        -0.70710678f, -0.77301045f, -0.83146961f, -0.88192126f, -0.92387953f, -0.95694034f, -0.98078528f, -0.99518473f, \
        -1.00000000f, -0.99518473f, -0.98078528f, -0.95694034f, -0.92387953f, -0.88192126f, -0.83146961f, -0.77301045f, \
        -0.70710678f, -0.63439328f, -0.55557023f, -0.47139674f, -0.38268343f, -0.29028468f, -0.19509032f, -0.09801714f, \
         0.00000000f,  0.09801714f,  0.19509032f,  0.29028468f,  0.38268343f,  0.47139674f,  0.55557023f,  0.63439328f, \
         0.70710678f,  0.77301045f,  0.83146961f,  0.88192126f,  0.92387953f,  0.95694034f,  0.98078528f,  0.99518473f, \
         1.00000000f,  0.99518473f,  0.98078528f,  0.95694034f,  0.92387953f,  0.88192126f,  0.83146961f,  0.77301045f, \
         0.70710678f,  0.63439328f,  0.55557023f,  0.47139674f,  0.38268343f,  0.29028468f,  0.19509032f,  0.09801714f };

// Complex FFT-16, natural order in/out (radix-4 x radix-4).
__device__ __forceinline__ void fft16c(float* ar, float* ai) {
    W16_TABLES
    float zr[16], zi[16];
    {
        float t0r = ar[0] + ar[8],  t0i = ai[0] + ai[8];
        float t1r = ar[0] - ar[8],  t1i = ai[0] - ai[8];
        float t2r = ar[4] + ar[12], t2i = ai[4] + ai[12];
        float t3r = ar[4] - ar[12], t3i = ai[4] - ai[12];
        zr[0] = t0r + t2r; zi[0] = t0i + t2i;
        zr[1] = t1r + t3i; zi[1] = t1i - t3r;
        zr[2] = t0r - t2r; zi[2] = t0i - t2i;
        zr[3] = t1r - t3i; zi[3] = t1i + t3r;
    }
#pragma unroll
    for (int a = 1; a < 4; a++) {
        float t0r = ar[a] + ar[a+8],  t0i = ai[a] + ai[a+8];
        float t1r = ar[a] - ar[a+8],  t1i = ai[a] - ai[a+8];
        float t2r = ar[a+4] + ar[a+12], t2i = ai[a+4] + ai[a+12];
        float t3r = ar[a+4] - ar[a+12], t3i = ai[a+4] - ai[a+12];
        float y1r = t1r + t3i, y1i = t1i - t3r;
        float y2r = t0r - t2r, y2i = t0i - t2i;
        float y3r = t1r - t3i, y3i = t1i + t3r;
        zr[4*a+0] = t0r + t2r; zi[4*a+0] = t0i + t2i;
        { const float c = C[a], s = S[a];
          zr[4*a+1] = c*y1r - s*y1i; zi[4*a+1] = c*y1i + s*y1r; }
        { const float c = C[(2*a)&15], s = S[(2*a)&15];
          zr[4*a+2] = c*y2r - s*y2i; zi[4*a+2] = c*y2i + s*y2r; }
        { const float c = C[(3*a)&15], s = S[(3*a)&15];
          zr[4*a+3] = c*y3r - s*y3i; zi[4*a+3] = c*y3i + s*y3r; }
    }
#pragma unroll
    for (int k2 = 0; k2 < 4; k2++) {
        float t0r = zr[k2]   + zr[k2+8],  t0i = zi[k2]   + zi[k2+8];
        float t1r = zr[k2]   - zr[k2+8],  t1i = zi[k2]   - zi[k2+8];
        float t2r = zr[k2+4] + zr[k2+12], t2i = zi[k2+4] + zi[k2+12];
        float t3r = zr[k2+4] - zr[k2+12], t3i = zi[k2+4] - zi[k2+12];
        ar[k2]    = t0r + t2r;  ai[k2]    = t0i + t2i;
        ar[k2+4]  = t1r + t3i;  ai[k2+4]  = t1i - t3r;
        ar[k2+8]  = t0r - t2r;  ai[k2+8]  = t0i - t2i;
        ar[k2+12] = t1r - t3i;  ai[k2+12] = t1i + t3r;
    }
}

// Stage-A twiddle: multiply regs j=1..15 by w^j, w = exp(i*base); sincos per j.
__device__ __forceinline__ void twiddle15p(float* ar, float* ai, float base) {
#pragma unroll
    for (int j = 1; j < 16; j++) {
        float s, c;
        __sincosf(base * (float)j, &s, &c);
        float tr = c * ar[j] - s * ai[j];
        ai[j]    = c * ai[j] + s * ar[j];
        ar[j]    = tr;
    }
}

// Stage-B twiddle: regs j=1..15 *= W_64^{M1*j}, from literal float table
// (indices compile-time -> pure FFMA-immediate sequences).
template <int M1>
__device__ __forceinline__ void twiddleB(float* ar, float* ai) {
    W64_TABLES
#pragma unroll
    for (int j = 1; j < 16; j++) {
        const float c = C64[(M1 * j) & 63];
        const float s = S64[(M1 * j) & 63];
        float tr = c * ar[j] - s * ai[j];
        ai[j]    = c * ai[j] + s * ar[j];
        ar[j]    = tr;
    }
}

__global__ __launch_bounds__(TPB, 24)
void fft1024_kernel(const float* __restrict__ x, float* __restrict__ out) {
    __shared__ __align__(16) float2 smem[BUFSZ];

    const int t    = threadIdx.x;       // 0..63
    const int pair = blockIdx.x;
    const int rowA = 2 * pair;

    float2* sm  = smem;
    float*  lin = (float*)sm;

    // ---- stage rows a,b into smem via cp.async (coalesced, bounded MLP) ----
    {
        const float4* xa4 = (const float4*)(x + (size_t)rowA * N_FFT);
        unsigned sbase = (unsigned)__cvta_generic_to_shared(lin);
#pragma unroll
        for (int c = 0; c < 8; c++) {               // c<4: row a, c>=4: row b
            int f = t + 64 * c;
            asm volatile("cp.async.cg.shared.global [%0], [%1], 16;\n"
                         :: "r"(sbase + f * 16), "l"(xa4 + f));
        }
        asm volatile("cp.async.commit_group;\n");
        asm volatile("cp.async.wait_group 0;\n");
    }
    __syncthreads();

    // z[n] = xa[n] + i*xb[n]; lane = n1 = t, regs over n2
    float ar[16], ai[16];
#pragma unroll
    for (int n2 = 0; n2 < 16; n2++) {
        ar[n2] = lin[t + 64 * n2];
        ai[n2] = lin[1024 + t + 64 * n2];
    }
    __syncthreads();   // reads done before ex1 overwrites

    // stage A: FFT-16 over n2 -> k2, twiddle W_1024^{t*k2}
    fft16c(ar, ai);
    twiddle15p(ar, ai, (float)t * (-6.2831853071795864769f / 1024.0f));

    // ex1: [n1 = t][k2 = j]
#pragma unroll
    for (int j = 0; j < 16; j++)
        sm[t * S1 + j] = make_float2(ar[j], ai[j]);
    __syncthreads();

    // stage B: thread = (m1, k2); n1 = m1 + 4*m2
    const int m1 = t >> 4;
    const int k2 = t & 15;
#pragma unroll
    for (int m2 = 0; m2 < 16; m2++) {
        float2 v = sm[(m1 + 4 * m2) * S1 + k2];
        ar[m2] = v.x; ai[m2] = v.y;
    }
    __syncthreads();

    fft16c(ar, ai);

    // W_64^{m1*j} via literal-immediate arms (m1=0: identity)
    if (m1 == 1)      twiddleB<1>(ar, ai);
    else if (m1 == 2) twiddleB<2>(ar, ai);
    else if (m1 == 3) twiddleB<3>(ar, ai);

    // ex2: [(m1*16 + j2)][k2]
#pragma unroll
    for (int j = 0; j < 16; j++)
        sm[(m1 * 16 + j) * S1 + k2] = make_float2(ar[j], ai[j]);
    __syncthreads();

    // stage C: thread = (j2 = t>>2, cq = t&3) handles k2 in {4cq..4cq+3};
    // FFT-4 over m1 -> j1; write Z[k] to ex3 at PHYS(k), k = 256*j1+16*j2+4cq+d
    {
        const int j2 = t >> 2;
        const int cq = t & 3;
        float br[4][4], bi[4][4];
#pragma unroll
        for (int mm = 0; mm < 4; mm++) {
#pragma unroll
            for (int d = 0; d < 4; d++) {
                float2 v = sm[(mm * 16 + j2) * S1 + 4 * cq + d];
                br[mm][d] = v.x; bi[mm][d] = v.y;
            }
        }
        __syncthreads();   // ex2 reads done before ex3 overwrites

        const int kb0 = 16 * j2 + 4 * cq;
#pragma unroll
        for (int d = 0; d < 4; d++) {
            float t0r = br[0][d] + br[2][d], t0i = bi[0][d] + bi[2][d];
            float t1r = br[0][d] - br[2][d], t1i = bi[0][d] - bi[2][d];
            float t2r = br[1][d] + br[3][d], t2i = bi[1][d] + bi[3][d];
            float t3r = br[1][d] - br[3][d], t3i = bi[1][d] - bi[3][d];
            const int kb = kb0 + d;
            sm[PHYS(kb      )] = make_float2(t0r + t2r, t0i + t2i);
            sm[PHYS(kb + 256)] = make_float2(t1r + t3i, t1i - t3r);
            sm[PHYS(kb + 512)] = make_float2(t0r - t2r, t0i - t2i);
            sm[PHYS(kb + 768)] = make_float2(t1r - t3i, t1i + t3r);
        }
    }
    __syncthreads();

    // ---- Hermitian unpack + coalesced float4 stores ----
    float* oRa = out + (size_t)rowA * N_FFT;
    float* oIa = out + (size_t)BATCH * N_FFT + (size_t)rowA * N_FFT;
    float* oRb = oRa + N_FFT;
    float* oIb = oIa + N_FFT;

#pragma unroll
    for (int u = 0; u < 4; u++) {
        const int k0 = 256 * u + 4 * t;
        const int km0 = (N_FFT - k0) & (N_FFT - 1);   // mirror of k0 (d=0)
        float4 xar, xai, xbr, xbi;
        float* pxar = &xar.x; float* pxai = &xai.x;
        float* pxbr = &xbr.x; float* pxbi = &xbi.x;
#pragma unroll
        for (int d = 0; d < 4; d++) {
            const int k  = k0 + d;
            const int km = (km0 - d) & (N_FFT - 1);
            float2 Z = sm[PHYS(k)];
            float2 M = sm[PHYS(km)];
            pxar[d] = 0.5f * (Z.x + M.x);
            pxai[d] = 0.5f * (Z.y - M.y);
            pxbr[d] = 0.5f * (Z.y + M.y);
            pxbi[d] = 0.5f * (M.x - Z.x);
        }
        *(float4*)(oRa + k0) = xar;
        *(float4*)(oIa + k0) = xai;
        *(float4*)(oRb + k0) = xbr;
        *(float4*)(oIb + k0) = xbi;
    }
}

extern "C" void kernel_launch(void* const* d_in, const int* in_sizes, int n_in,
                              void* d_out, int out_size) {
    const float* x = (const float*)d_in[0];
    float* out = (float*)d_out;
    fft1024_kernel<<<BATCH / 2, TPB>>>(x, out);
}